// round 3
// baseline (speedup 1.0000x reference)
#include <cuda_runtime.h>
#include <cstdio>

#define HD 128
#define MAXN 50048
#define MAXB 128
#define BN_EPS 1e-5f

// ---------------- scratch (no allocations allowed) ----------------
__device__ float g_agg [MAXN * HD];
__device__ float g_h   [MAXN * HD];
__device__ float g_x   [MAXN * HD];
__device__ float g_stats[2 * HD];   // [0:128) sum, [128:256) sumsq
__device__ float g_bn   [2 * HD];   // [0:128) scale, [128:256) shift
__device__ float g_pool [MAXB * HD];
__device__ float g_t1   [MAXB * HD];

// ---------------- helpers ----------------
__device__ __forceinline__ void red_add_v4(float* p, float4 v) {
    asm volatile("red.global.add.v4.f32 [%0], {%1,%2,%3,%4};"
                 :: "l"(p), "f"(v.x), "f"(v.y), "f"(v.z), "f"(v.w) : "memory");
}

// ---------------- init: agg = x ((1+eps)*x_i term, eps=0) + zero bn stats ----------------
__global__ void k_init(const float* __restrict__ x, int n4) {
    int i = blockIdx.x * blockDim.x + threadIdx.x;
    if (blockIdx.x == 0 && threadIdx.x < 2 * HD) g_stats[threadIdx.x] = 0.f;
    if (i < n4) reinterpret_cast<float4*>(g_agg)[i] =
                reinterpret_cast<const float4*>(x)[i];
}

// ---------------- edge scatter: agg[dst] += x[src]  (warp per edge) ----------------
__global__ __launch_bounds__(256)
void k_scatter(const int* __restrict__ src, const int* __restrict__ dst,
               const float* __restrict__ x, int E) {
    int w    = (blockIdx.x * blockDim.x + threadIdx.x) >> 5;
    int lane = threadIdx.x & 31;
    if (w >= E) return;
    int s = __ldg(src + w);
    int d = __ldg(dst + w);
    float4 v = reinterpret_cast<const float4*>(x)[s * 32 + lane];
    red_add_v4(g_agg + d * HD + lane * 4, v);
}

// ---------------- main GEMM: Out[N,128] = f(A)[N,128] @ W[128,128] + b ----------------
// BN_IN:    A element -> relu(a*scale[k] + shift[k])   (fused BN+ReLU input)
// RELU_OUT: relu on output
// STATS:    accumulate per-column sum / sumsq of Out into g_stats (pre-BN h)
template <bool BN_IN, bool RELU_OUT, bool STATS>
__global__ __launch_bounds__(256)
void k_gemm(const float* __restrict__ A, const float* __restrict__ W,
            const float* __restrict__ bias, float* __restrict__ Out, int N) {
    __shared__ float sA[64][32];
    __shared__ float sW[32][128];
    __shared__ float ssum[128];
    __shared__ float ssq [128];

    const int tid  = threadIdx.x;
    const int tx   = tid & 31;       // column group: cols tx*4 .. tx*4+3
    const int ty   = tid >> 5;       // row group  : rows ty*8 .. ty*8+7
    const int row0 = blockIdx.x * 64;

    float acc[8][4];
#pragma unroll
    for (int i = 0; i < 8; i++)
#pragma unroll
        for (int j = 0; j < 4; j++) acc[i][j] = 0.f;

#pragma unroll
    for (int kt = 0; kt < 4; kt++) {
        // --- load A tile (64 x 32) ---
        {
            int r = tid >> 2;            // 0..63
            int c = (tid & 3) * 8;       // 0,8,16,24
            int grow = row0 + r;
            float4 v0 = {0, 0, 0, 0}, v1 = {0, 0, 0, 0};
            if (grow < N) {
                const float* ap = A + grow * HD + kt * 32 + c;
                v0 = *reinterpret_cast<const float4*>(ap);
                v1 = *reinterpret_cast<const float4*>(ap + 4);
                if (BN_IN) {
                    int k = kt * 32 + c;
                    v0.x = fmaxf(fmaf(v0.x, g_bn[k + 0], g_bn[HD + k + 0]), 0.f);
                    v0.y = fmaxf(fmaf(v0.y, g_bn[k + 1], g_bn[HD + k + 1]), 0.f);
                    v0.z = fmaxf(fmaf(v0.z, g_bn[k + 2], g_bn[HD + k + 2]), 0.f);
                    v0.w = fmaxf(fmaf(v0.w, g_bn[k + 3], g_bn[HD + k + 3]), 0.f);
                    v1.x = fmaxf(fmaf(v1.x, g_bn[k + 4], g_bn[HD + k + 4]), 0.f);
                    v1.y = fmaxf(fmaf(v1.y, g_bn[k + 5], g_bn[HD + k + 5]), 0.f);
                    v1.z = fmaxf(fmaf(v1.z, g_bn[k + 6], g_bn[HD + k + 6]), 0.f);
                    v1.w = fmaxf(fmaf(v1.w, g_bn[k + 7], g_bn[HD + k + 7]), 0.f);
                }
            }
            *reinterpret_cast<float4*>(&sA[r][c])     = v0;
            *reinterpret_cast<float4*>(&sA[r][c + 4]) = v1;
        }
        // --- load W tile (32 x 128) ---
        {
            int wr = tid >> 3;           // 0..31
            int wc = (tid & 7) * 16;     // 0,16,...,112
            const float* wp = W + (kt * 32 + wr) * HD + wc;
#pragma unroll
            for (int q = 0; q < 4; q++)
                *reinterpret_cast<float4*>(&sW[wr][wc + q * 4]) =
                    *reinterpret_cast<const float4*>(wp + q * 4);
        }
        __syncthreads();

#pragma unroll
        for (int k = 0; k < 32; k++) {
            float4 wv = *reinterpret_cast<float4*>(&sW[k][tx * 4]);
#pragma unroll
            for (int i = 0; i < 8; i++) {
                float av = sA[ty * 8 + i][k];
                acc[i][0] = fmaf(av, wv.x, acc[i][0]);
                acc[i][1] = fmaf(av, wv.y, acc[i][1]);
                acc[i][2] = fmaf(av, wv.z, acc[i][2]);
                acc[i][3] = fmaf(av, wv.w, acc[i][3]);
            }
        }
        __syncthreads();
    }

    if (STATS) {
        if (tid < 128) { ssum[tid] = 0.f; ssq[tid] = 0.f; }
        __syncthreads();
    }

    float4 b = *reinterpret_cast<const float4*>(bias + tx * 4);
    float csum[4] = {0, 0, 0, 0}, csq[4] = {0, 0, 0, 0};
#pragma unroll
    for (int i = 0; i < 8; i++) {
        int grow = row0 + ty * 8 + i;
        if (grow < N) {
            float4 o;
            o.x = acc[i][0] + b.x;
            o.y = acc[i][1] + b.y;
            o.z = acc[i][2] + b.z;
            o.w = acc[i][3] + b.w;
            if (RELU_OUT) {
                o.x = fmaxf(o.x, 0.f); o.y = fmaxf(o.y, 0.f);
                o.z = fmaxf(o.z, 0.f); o.w = fmaxf(o.w, 0.f);
            }
            *reinterpret_cast<float4*>(Out + grow * HD + tx * 4) = o;
            if (STATS) {
                csum[0] += o.x; csum[1] += o.y; csum[2] += o.z; csum[3] += o.w;
                csq[0]  += o.x * o.x; csq[1] += o.y * o.y;
                csq[2]  += o.z * o.z; csq[3] += o.w * o.w;
            }
        }
    }
    if (STATS) {
#pragma unroll
        for (int j = 0; j < 4; j++) {
            atomicAdd(&ssum[tx * 4 + j], csum[j]);
            atomicAdd(&ssq [tx * 4 + j], csq[j]);
        }
        __syncthreads();
        if (tid < 128) {
            atomicAdd(&g_stats[tid],      ssum[tid]);
            atomicAdd(&g_stats[HD + tid], ssq[tid]);
        }
    }
}

// ---------------- BN finalize: scale/shift from batch stats ----------------
__global__ void k_bnfin(const float* __restrict__ bn_g, const float* __restrict__ bn_b,
                        int l, float invN) {
    int c = threadIdx.x;   // 128 threads
    float mu   = g_stats[c] * invN;
    float var  = g_stats[HD + c] * invN - mu * mu;
    float rstd = rsqrtf(var + BN_EPS);
    float s    = bn_g[l * HD + c] * rstd;
    g_bn[c]      = s;
    g_bn[HD + c] = bn_b[l * HD + c] - mu * s;
}

// ---------------- rec3: x_rec = relu(A @ W3[128,4] + b3)  (warp per node) ----------------
__global__ __launch_bounds__(256)
void k_rec3(const float* __restrict__ A, const float* __restrict__ W3,
            const float* __restrict__ b3, float* __restrict__ out, int N) {
    int w    = (blockIdx.x * blockDim.x + threadIdx.x) >> 5;
    int lane = threadIdx.x & 31;
    if (w >= N) return;
    float4 v = reinterpret_cast<const float4*>(A)[w * 32 + lane];
    int k = lane * 4;
    float4 w0 = reinterpret_cast<const float4*>(W3)[k + 0];
    float4 w1 = reinterpret_cast<const float4*>(W3)[k + 1];
    float4 w2 = reinterpret_cast<const float4*>(W3)[k + 2];
    float4 w3 = reinterpret_cast<const float4*>(W3)[k + 3];
    float s0 = v.x * w0.x + v.y * w1.x + v.z * w2.x + v.w * w3.x;
    float s1 = v.x * w0.y + v.y * w1.y + v.z * w2.y + v.w * w3.y;
    float s2 = v.x * w0.z + v.y * w1.z + v.z * w2.z + v.w * w3.z;
    float s3 = v.x * w0.w + v.y * w1.w + v.z * w2.w + v.w * w3.w;
#pragma unroll
    for (int off = 16; off; off >>= 1) {
        s0 += __shfl_down_sync(0xffffffffu, s0, off);
        s1 += __shfl_down_sync(0xffffffffu, s1, off);
        s2 += __shfl_down_sync(0xffffffffu, s2, off);
        s3 += __shfl_down_sync(0xffffffffu, s3, off);
    }
    if (lane == 0) {
        float4 o;
        o.x = fmaxf(s0 + b3[0], 0.f);
        o.y = fmaxf(s1 + b3[1], 0.f);
        o.z = fmaxf(s2 + b3[2], 0.f);
        o.w = fmaxf(s3 + b3[3], 0.f);
        *reinterpret_cast<float4*>(out + w * 4) = o;
    }
}

// ---------------- pool zero + pool ----------------
__global__ void k_zeropool(int n) {
    int i = blockIdx.x * blockDim.x + threadIdx.x;
    if (i < n) g_pool[i] = 0.f;
}
__global__ __launch_bounds__(256)
void k_pool(const float* __restrict__ x, const int* __restrict__ batch, int N) {
    int w    = (blockIdx.x * blockDim.x + threadIdx.x) >> 5;
    int lane = threadIdx.x & 31;
    if (w >= N) return;
    int b = __ldg(batch + w);
    float4 v = reinterpret_cast<const float4*>(x)[w * 32 + lane];
    red_add_v4(g_pool + b * HD + lane * 4, v);
}

// ---------------- tiny dense MLP: out[B,M] = f(A[B,128] @ W[128,M] + b) ----------------
template <bool RELU>
__global__ void k_fmlp(const float* __restrict__ A, const float* __restrict__ W,
                       const float* __restrict__ bias, float* __restrict__ out,
                       int B, int M) {
    int idx = blockIdx.x * blockDim.x + threadIdx.x;
    int r = idx / M, c = idx % M;
    if (r >= B) return;
    float s = bias[c];
    const float* a = A + r * HD;
#pragma unroll 8
    for (int k = 0; k < HD; k++) s = fmaf(a[k], W[k * M + c], s);
    out[idx] = RELU ? fmaxf(s, 0.f) : s;
}

// ---------------- launcher ----------------
extern "C" void kernel_launch(void* const* d_in, const int* in_sizes, int n_in,
                              void* d_out, int out_size) {
    const float* x_in   = (const float*)d_in[0];
    const int*   ei     = (const int*)  d_in[1];
    const int*   batch  = (const int*)  d_in[2];
    const float* convW1 = (const float*)d_in[3];
    const float* convb1 = (const float*)d_in[4];
    const float* bn_g   = (const float*)d_in[5];
    const float* bn_b   = (const float*)d_in[6];
    const float* convW2 = (const float*)d_in[7];
    const float* convb2 = (const float*)d_in[8];
    const float* recW1  = (const float*)d_in[9];
    const float* recb1  = (const float*)d_in[10];
    const float* recW2  = (const float*)d_in[11];
    const float* recb2  = (const float*)d_in[12];
    const float* recW3  = (const float*)d_in[13];
    const float* recb3  = (const float*)d_in[14];
    const float* mlpW1  = (const float*)d_in[15];
    const float* mlpb1  = (const float*)d_in[16];
    const float* mlpW2  = (const float*)d_in[17];
    const float* mlpb2  = (const float*)d_in[18];

    const int N = in_sizes[0] / HD;
    const int E = in_sizes[1] / 2;
    const int B = (out_size - 4 * N) / 64;        // 64
    const int* src = ei;
    const int* dst = ei + E;

    float* out_final = (float*)d_out;             // [B,64]
    float* x_rec     = (float*)d_out + B * 64;    // [N,4]

    float *p_agg, *p_h, *p_x, *p_pool, *p_t1;
    cudaGetSymbolAddress((void**)&p_agg,  g_agg);
    cudaGetSymbolAddress((void**)&p_h,    g_h);
    cudaGetSymbolAddress((void**)&p_x,    g_x);
    cudaGetSymbolAddress((void**)&p_pool, g_pool);
    cudaGetSymbolAddress((void**)&p_t1,   g_t1);

    const int gemm_blocks = (N + 63) / 64;
    const int n4 = N * (HD / 4);

    const float* xcur = x_in;
    for (int l = 0; l < 3; l++) {
        k_init<<<(n4 + 255) / 256, 256>>>(xcur, n4);
        k_scatter<<<(E + 7) / 8, 256>>>(src, dst, xcur, E);
        k_gemm<false, false, true><<<gemm_blocks, 256>>>(
            p_agg, convW1 + l * HD * HD, convb1 + l * HD, p_h, N);
        k_bnfin<<<1, 128>>>(bn_g, bn_b, l, 1.0f / (float)N);
        k_gemm<true, true, false><<<gemm_blocks, 256>>>(
            p_h, convW2 + l * HD * HD, convb2 + l * HD, p_x, N);
        xcur = p_x;
    }

    // reconstruction head
    k_gemm<false, true, false><<<gemm_blocks, 256>>>(p_x, recW1, recb1, p_agg, N);
    k_gemm<false, true, false><<<gemm_blocks, 256>>>(p_agg, recW2, recb2, p_h, N);
    k_rec3<<<(N + 7) / 8, 256>>>(p_h, recW3, recb3, x_rec, N);

    // pooled head
    k_zeropool<<<(B * HD + 255) / 256, 256>>>(B * HD);
    k_pool<<<(N + 7) / 8, 256>>>(p_x, batch, N);
    k_fmlp<true ><<<(B * HD + 255) / 256, 256>>>(p_pool, mlpW1, mlpb1, p_t1, B, HD);
    k_fmlp<false><<<(B * 64 + 255) / 256, 256>>>(p_t1, mlpW2, mlpb2, out_final, B, 64);
}

// round 13
// speedup vs baseline: 1.0017x; 1.0017x over previous
#include <cuda_runtime.h>
#include <cstdint>
#include <cstdio>

#define HD 128
#define MAXN 50048
#define MAXB 128
#define BN_EPS 1e-5f

// ---------------- scratch (no allocations allowed) ----------------
__device__ float g_agg [MAXN * HD];
__device__ float g_h   [MAXN * HD];
__device__ float g_x   [MAXN * HD];
__device__ float g_stats[2 * HD];
__device__ float g_bn   [2 * HD];
__device__ float g_pool [MAXB * HD];
__device__ float g_t1   [MAXB * HD];
// fragment-packed tf32 weights: 8 matrices x (hi 16384 + lo 16384) u32 entries
__device__ uint32_t g_wpu[8 * 2 * 16384];

// ---------------- helpers ----------------
__device__ __forceinline__ uint32_t tf32_of(float v) {
    uint32_t r;
    asm("cvt.rna.tf32.f32 %0, %1;" : "=r"(r) : "f"(v));
    return r;
}
// tf32 3-pass split: hi = tf32(v), lo = tf32(v - float(hi))
__device__ __forceinline__ uint32_t tf32_lo(float v, uint32_t hi) {
    return tf32_of(v - __uint_as_float(hi));
}
__device__ __forceinline__ void mma_tf32(float* d, uint32_t a0, uint32_t a1, uint32_t a2,
                                         uint32_t a3, uint32_t b0, uint32_t b1) {
    asm volatile("mma.sync.aligned.m16n8k8.row.col.f32.tf32.tf32.f32 "
                 "{%0,%1,%2,%3}, {%4,%5,%6,%7}, {%8,%9}, {%0,%1,%2,%3};"
                 : "+f"(d[0]), "+f"(d[1]), "+f"(d[2]), "+f"(d[3])
                 : "r"(a0), "r"(a1), "r"(a2), "r"(a3), "r"(b0), "r"(b1));
}
__device__ __forceinline__ void red_add_v4(float* p, float4 v) {
    asm volatile("red.global.add.v4.f32 [%0], {%1,%2,%3,%4};"
                 :: "l"(p), "f"(v.x), "f"(v.y), "f"(v.z), "f"(v.w) : "memory");
}

// SMEM layout (fp32 A: row stride 136 floats = 544 B)
#define AROW 544
#define SM_BIAS 0
#define SM_BN   512
#define SM_WHI  2048
#define SM_WLO  (SM_WHI + 65536)
#define SM_A    (SM_WLO + 65536)
#define SM_TOTAL (SM_A + 128 * AROW)

// ---------------- weight prepack: fragment-ordered tf32 b-reg images ----------------
// i = ((ks*16 + nt)*32 + lane)*2 + j, j in {0,1}:
//   k = ks*8 + (lane&3) + j*4 ; n = nt*8 + (lane>>2)
__global__ void k_prepw(const float* __restrict__ c1, const float* __restrict__ c2,
                        const float* __restrict__ r1, const float* __restrict__ r2) {
    int m = blockIdx.x;
    const float* W = (m < 3) ? c1 + m * 16384
                   : (m < 6) ? c2 + (m - 3) * 16384
                   : (m == 6) ? r1 : r2;
    uint32_t* hi = g_wpu + m * 32768;
    uint32_t* lo = hi + 16384;
    for (int i = threadIdx.x; i < 16384; i += blockDim.x) {
        int j = i & 1, slot = i >> 1;
        int lane = slot & 31, nt = (slot >> 5) & 15, ks = slot >> 9;
        int k = ks * 8 + (lane & 3) + j * 4;
        int n = nt * 8 + (lane >> 2);
        float w = W[k * HD + n];
        uint32_t h = tf32_of(w);
        hi[i] = h;
        lo[i] = tf32_lo(w, h);
    }
}

// ---------------- tf32x3 MMA GEMM: Out[N,128] = f(A)[N,128] @ W[128,128] + b -----------
// D = Ahi@Whi + Ahi@Wlo + Alo@Whi (22-bit effective precision)
template <bool BN_IN, bool RELU_OUT>
__global__ __launch_bounds__(256)
void k_tgemm(const float* __restrict__ A, const uint32_t* __restrict__ wpk,
             const float* __restrict__ bias, float* __restrict__ Out, int N) {
    extern __shared__ char smem[];
    const int tid  = threadIdx.x;
    const int wid  = tid >> 5;
    const int lane = tid & 31;
    const int row0 = blockIdx.x * 128;

    if (tid < 128) ((float*)(smem + SM_BIAS))[tid] = bias[tid];
    if (BN_IN && tid < 128) {
        ((float*)(smem + SM_BN))[tid]       = g_bn[tid];
        ((float*)(smem + SM_BN))[tid + 128] = g_bn[tid + 128];
    }
    // copy W fragment images (linear, 4096 uint4 each)
    {
        const uint4* sh = (const uint4*)wpk;            // hi
        const uint4* sl = (const uint4*)(wpk + 16384);  // lo
        uint4* dh = (uint4*)(smem + SM_WHI);
        uint4* dl = (uint4*)(smem + SM_WLO);
#pragma unroll
        for (int i = 0; i < 16; i++) {
            dh[tid + i * 256] = sh[tid + i * 256];
            dl[tid + i * 256] = sl[tid + i * 256];
        }
    }
    // stage A as fp32 (BN+ReLU fused here when enabled)
    const float* sbn = (const float*)(smem + SM_BN);
#pragma unroll
    for (int it = 0; it < 8; it++) {
        int idx = tid + it * 256;        // 0..2047
        int r  = idx >> 4;
        int c0 = (idx & 15) * 8;
        float4 v0 = {0, 0, 0, 0}, v1 = {0, 0, 0, 0};
        int gr = row0 + r;
        if (gr < N) {
            const float4* ap = (const float4*)(A + gr * HD + c0);
            v0 = ap[0]; v1 = ap[1];
            if (BN_IN) {
                v0.x = fmaxf(fmaf(v0.x, sbn[c0 + 0], sbn[128 + c0 + 0]), 0.f);
                v0.y = fmaxf(fmaf(v0.y, sbn[c0 + 1], sbn[128 + c0 + 1]), 0.f);
                v0.z = fmaxf(fmaf(v0.z, sbn[c0 + 2], sbn[128 + c0 + 2]), 0.f);
                v0.w = fmaxf(fmaf(v0.w, sbn[c0 + 3], sbn[128 + c0 + 3]), 0.f);
                v1.x = fmaxf(fmaf(v1.x, sbn[c0 + 4], sbn[128 + c0 + 4]), 0.f);
                v1.y = fmaxf(fmaf(v1.y, sbn[c0 + 5], sbn[128 + c0 + 5]), 0.f);
                v1.z = fmaxf(fmaf(v1.z, sbn[c0 + 6], sbn[128 + c0 + 6]), 0.f);
                v1.w = fmaxf(fmaf(v1.w, sbn[c0 + 7], sbn[128 + c0 + 7]), 0.f);
            }
        }
        *(float4*)(smem + SM_A + r * AROW + c0 * 4)      = v0;
        *(float4*)(smem + SM_A + r * AROW + c0 * 4 + 16) = v1;
    }
    __syncthreads();

    // ---- mainloop: warp w -> rows [w*16, w*16+16), 16 n-tiles of 8 cols ----
    float acc[16][4];
#pragma unroll
    for (int t = 0; t < 16; t++)
#pragma unroll
        for (int j = 0; j < 4; j++) acc[t][j] = 0.f;

    // A fragment addresses (m16n8k8 tf32, by definition):
    //   a0: (row wid*16 + lane>>2, col ks*8 + lane&3); a1: row+8; a2: col+4; a3: both
    const char* a_base = smem + SM_A + (wid * 16 + (lane >> 2)) * AROW + (lane & 3) * 4;
    const char* w_hi   = smem + SM_WHI + lane * 8;
    const char* w_lo   = smem + SM_WLO + lane * 8;

#pragma unroll
    for (int ks = 0; ks < 16; ks++) {
        const char* ap = a_base + ks * 32;           // ks*8 cols * 4B
        float fa = *(const float*)(ap);
        float fb = *(const float*)(ap + 8 * AROW);
        float fc = *(const float*)(ap + 16);         // col +4
        float fd = *(const float*)(ap + 8 * AROW + 16);
        uint32_t h0 = tf32_of(fa), h1 = tf32_of(fb), h2 = tf32_of(fc), h3 = tf32_of(fd);
        uint32_t l0 = tf32_lo(fa, h0), l1 = tf32_lo(fb, h1),
                 l2 = tf32_lo(fc, h2), l3 = tf32_lo(fd, h3);
#pragma unroll
        for (int nt = 0; nt < 16; nt++) {
            int slot = (ks * 16 + nt) * 256;         // *32 lanes *8 B
            uint2 wh = *(const uint2*)(w_hi + slot);
            uint2 wl = *(const uint2*)(w_lo + slot);
            mma_tf32(acc[nt], h0, h1, h2, h3, wh.x, wh.y);
            mma_tf32(acc[nt], h0, h1, h2, h3, wl.x, wl.y);
            mma_tf32(acc[nt], l0, l1, l2, l3, wh.x, wh.y);
        }
    }

    // ---- epilogue: bias (+relu), store ----
    const float* sbias = (const float*)(smem + SM_BIAS);
    int r_lo = row0 + wid * 16 + (lane >> 2);
    int r_hi = r_lo + 8;
#pragma unroll
    for (int t = 0; t < 16; t++) {
        int c = t * 8 + (lane & 3) * 2;
        float bx = sbias[c], by = sbias[c + 1];
        float2 o0, o1;
        o0.x = acc[t][0] + bx; o0.y = acc[t][1] + by;
        o1.x = acc[t][2] + bx; o1.y = acc[t][3] + by;
        if (RELU_OUT) {
            o0.x = fmaxf(o0.x, 0.f); o0.y = fmaxf(o0.y, 0.f);
            o1.x = fmaxf(o1.x, 0.f); o1.y = fmaxf(o1.y, 0.f);
        }
        if (r_lo < N) *(float2*)(Out + r_lo * HD + c) = o0;
        if (r_hi < N) *(float2*)(Out + r_hi * HD + c) = o1;
    }
}

// ---------------- init: agg = x + zero bn stats ----------------
__global__ void k_init(const float* __restrict__ x, int n4) {
    int i = blockIdx.x * blockDim.x + threadIdx.x;
    if (blockIdx.x == 0 && threadIdx.x < 2 * HD) g_stats[threadIdx.x] = 0.f;
    if (i < n4) reinterpret_cast<float4*>(g_agg)[i] =
                reinterpret_cast<const float4*>(x)[i];
}

// ---------------- edge scatter: agg[dst] += x[src] ----------------
__global__ __launch_bounds__(256)
void k_scatter(const int* __restrict__ src, const int* __restrict__ dst,
               const float* __restrict__ x, int E) {
    int w    = (blockIdx.x * blockDim.x + threadIdx.x) >> 5;
    int lane = threadIdx.x & 31;
    if (w >= E) return;
    int s = __ldg(src + w);
    int d = __ldg(dst + w);
    float4 v = reinterpret_cast<const float4*>(x)[s * 32 + lane];
    red_add_v4(g_agg + d * HD + lane * 4, v);
}

// ---------------- column stats: sum & sumsq of h ----------------
__global__ __launch_bounds__(256)
void k_stats(const float* __restrict__ h, int N) {
    int c    = threadIdx.x & 127;
    int half = threadIdx.x >> 7;
    float s = 0.f, q = 0.f;
    for (int r = blockIdx.x * 2 + half; r < N; r += gridDim.x * 2) {
        float v = h[r * HD + c];
        s += v; q += v * v;
    }
    atomicAdd(&g_stats[c], s);
    atomicAdd(&g_stats[HD + c], q);
}

// ---------------- BN finalize ----------------
__global__ void k_bnfin(const float* __restrict__ bn_g, const float* __restrict__ bn_b,
                        int l, float invN) {
    int c = threadIdx.x;
    float mu   = g_stats[c] * invN;
    float var  = g_stats[HD + c] * invN - mu * mu;
    float rstd = rsqrtf(var + BN_EPS);
    float s    = bn_g[l * HD + c] * rstd;
    g_bn[c]      = s;
    g_bn[HD + c] = bn_b[l * HD + c] - mu * s;
}

// ---------------- rec3: x_rec = relu(A @ W3[128,4] + b3) ----------------
__global__ __launch_bounds__(256)
void k_rec3(const float* __restrict__ A, const float* __restrict__ W3,
            const float* __restrict__ b3, float* __restrict__ out, int N) {
    int w    = (blockIdx.x * blockDim.x + threadIdx.x) >> 5;
    int lane = threadIdx.x & 31;
    if (w >= N) return;
    float4 v = reinterpret_cast<const float4*>(A)[w * 32 + lane];
    int k = lane * 4;
    float4 w0 = reinterpret_cast<const float4*>(W3)[k + 0];
    float4 w1 = reinterpret_cast<const float4*>(W3)[k + 1];
    float4 w2 = reinterpret_cast<const float4*>(W3)[k + 2];
    float4 w3 = reinterpret_cast<const float4*>(W3)[k + 3];
    float s0 = v.x * w0.x + v.y * w1.x + v.z * w2.x + v.w * w3.x;
    float s1 = v.x * w0.y + v.y * w1.y + v.z * w2.y + v.w * w3.y;
    float s2 = v.x * w0.z + v.y * w1.z + v.z * w2.z + v.w * w3.z;
    float s3 = v.x * w0.w + v.y * w1.w + v.z * w2.w + v.w * w3.w;
#pragma unroll
    for (int off = 16; off; off >>= 1) {
        s0 += __shfl_down_sync(0xffffffffu, s0, off);
        s1 += __shfl_down_sync(0xffffffffu, s1, off);
        s2 += __shfl_down_sync(0xffffffffu, s2, off);
        s3 += __shfl_down_sync(0xffffffffu, s3, off);
    }
    if (lane == 0) {
        float4 o;
        o.x = fmaxf(s0 + b3[0], 0.f);
        o.y = fmaxf(s1 + b3[1], 0.f);
        o.z = fmaxf(s2 + b3[2], 0.f);
        o.w = fmaxf(s3 + b3[3], 0.f);
        *reinterpret_cast<float4*>(out + w * 4) = o;
    }
}

// ---------------- pool ----------------
__global__ void k_zeropool(int n) {
    int i = blockIdx.x * blockDim.x + threadIdx.x;
    if (i < n) g_pool[i] = 0.f;
}
__global__ __launch_bounds__(256)
void k_pool(const float* __restrict__ x, const int* __restrict__ batch, int N) {
    int w    = (blockIdx.x * blockDim.x + threadIdx.x) >> 5;
    int lane = threadIdx.x & 31;
    if (w >= N) return;
    int b = __ldg(batch + w);
    float4 v = reinterpret_cast<const float4*>(x)[w * 32 + lane];
    red_add_v4(g_pool + b * HD + lane * 4, v);
}

// ---------------- tiny dense MLP ----------------
template <bool RELU>
__global__ void k_fmlp(const float* __restrict__ A, const float* __restrict__ W,
                       const float* __restrict__ bias, float* __restrict__ out,
                       int B, int M) {
    int idx = blockIdx.x * blockDim.x + threadIdx.x;
    int r = idx / M, c = idx % M;
    if (r >= B) return;
    float s = bias[c];
    const float* a = A + r * HD;
#pragma unroll 8
    for (int k = 0; k < HD; k++) s = fmaf(a[k], W[k * M + c], s);
    out[idx] = RELU ? fmaxf(s, 0.f) : s;
}

// ---------------- launcher ----------------
extern "C" void kernel_launch(void* const* d_in, const int* in_sizes, int n_in,
                              void* d_out, int out_size) {
    const float* x_in   = (const float*)d_in[0];
    const int*   ei     = (const int*)  d_in[1];
    const int*   batch  = (const int*)  d_in[2];
    const float* convW1 = (const float*)d_in[3];
    const float* convb1 = (const float*)d_in[4];
    const float* bn_g   = (const float*)d_in[5];
    const float* bn_b   = (const float*)d_in[6];
    const float* convW2 = (const float*)d_in[7];
    const float* convb2 = (const float*)d_in[8];
    const float* recW1  = (const float*)d_in[9];
    const float* recb1  = (const float*)d_in[10];
    const float* recW2  = (const float*)d_in[11];
    const float* recb2  = (const float*)d_in[12];
    const float* recW3  = (const float*)d_in[13];
    const float* recb3  = (const float*)d_in[14];
    const float* mlpW1  = (const float*)d_in[15];
    const float* mlpb1  = (const float*)d_in[16];
    const float* mlpW2  = (const float*)d_in[17];
    const float* mlpb2  = (const float*)d_in[18];

    const int N = in_sizes[0] / HD;
    const int E = in_sizes[1] / 2;
    const int B = (out_size - 4 * N) / 64;
    const int* src = ei;
    const int* dst = ei + E;

    float* out_final = (float*)d_out;
    float* x_rec     = (float*)d_out + B * 64;

    float *p_agg, *p_h, *p_x, *p_pool, *p_t1;
    uint32_t* p_wp;
    cudaGetSymbolAddress((void**)&p_agg,  g_agg);
    cudaGetSymbolAddress((void**)&p_h,    g_h);
    cudaGetSymbolAddress((void**)&p_x,    g_x);
    cudaGetSymbolAddress((void**)&p_pool, g_pool);
    cudaGetSymbolAddress((void**)&p_t1,   g_t1);
    cudaGetSymbolAddress((void**)&p_wp,   g_wpu);

    cudaFuncSetAttribute(k_tgemm<false, false>,
                         cudaFuncAttributeMaxDynamicSharedMemorySize, SM_TOTAL);
    cudaFuncSetAttribute(k_tgemm<true, true>,
                         cudaFuncAttributeMaxDynamicSharedMemorySize, SM_TOTAL);
    cudaFuncSetAttribute(k_tgemm<false, true>,
                         cudaFuncAttributeMaxDynamicSharedMemorySize, SM_TOTAL);

    const int tg  = (N + 127) / 128;   // 391
    const int n4  = N * (HD / 4);

    k_prepw<<<8, 256>>>(convW1, convW2, recW1, recW2);

    const float* xcur = x_in;
    for (int l = 0; l < 3; l++) {
        k_init<<<(n4 + 255) / 256, 256>>>(xcur, n4);
        k_scatter<<<(E + 7) / 8, 256>>>(src, dst, xcur, E);
        k_tgemm<false, false><<<tg, 256, SM_TOTAL>>>(
            p_agg, p_wp + l * 32768, convb1 + l * HD, p_h, N);
        k_stats<<<148, 256>>>(p_h, N);
        k_bnfin<<<1, 128>>>(bn_g, bn_b, l, 1.0f / (float)N);
        k_tgemm<true, true><<<tg, 256, SM_TOTAL>>>(
            p_h, p_wp + (3 + l) * 32768, convb2 + l * HD, p_x, N);
        xcur = p_x;
    }

    // reconstruction head
    k_tgemm<false, true><<<tg, 256, SM_TOTAL>>>(p_x,   p_wp + 6 * 32768, recb1, p_agg, N);
    k_tgemm<false, true><<<tg, 256, SM_TOTAL>>>(p_agg, p_wp + 7 * 32768, recb2, p_h,   N);
    k_rec3<<<(N + 7) / 8, 256>>>(p_h, recW3, recb3, x_rec, N);

    // pooled head
    k_zeropool<<<(B * HD + 255) / 256, 256>>>(B * HD);
    k_pool<<<(N + 7) / 8, 256>>>(p_x, batch, N);
    k_fmlp<true ><<<(B * HD + 255) / 256, 256>>>(p_pool, mlpW1, mlpb1, p_t1, B, HD);
    k_fmlp<false><<<(B * 64 + 255) / 256, 256>>>(p_t1, mlpW2, mlpb2, out_final, B, 64);
}